// round 4
// baseline (speedup 1.0000x reference)
#include <cuda_runtime.h>
#include <cuda_bf16.h>
#include <cstdint>

// Problem constants (match reference_code)
#define NN 50000      // nodes
#define EE 800000     // edges
#define IN_F 128
#define DD 64
#define HH 4
#define HD 256        // H*D
#define NEG_SLOPE 0.2f

// ---------------------------------------------------------------------------
// Scratch (static __device__ arrays — no allocation allowed)
// ---------------------------------------------------------------------------
__device__ float g_feat[(size_t)NN * HD];   // projected features [N,256]
__device__ float g_h[(size_t)NN * HD];      // layer io buffer
__device__ float g_el[(size_t)NN * HH];
__device__ float g_er[(size_t)NN * HH];
__device__ int   g_rowptr[NN + 1];
__device__ int   g_cur[NN];
__device__ int   g_csr[EE];                 // src node per CSR slot (sorted by dst)
__device__ float g_Wh[IN_F * HD];           // tf32-high split of current layer W
__device__ float g_Wl[IN_F * HD];           // tf32-low  split of current layer W

// ---------------------------------------------------------------------------
// CSR build: zero -> histogram(dst) -> scan -> scatter
// ---------------------------------------------------------------------------
__global__ void zero_cur_k() {
    int i = blockIdx.x * blockDim.x + threadIdx.x;
    if (i < NN) g_cur[i] = 0;
}

__global__ void hist_k(const int* __restrict__ dst) {
    int e = blockIdx.x * blockDim.x + threadIdx.x;
    if (e < EE) atomicAdd(&g_cur[dst[e]], 1);
}

// single-block exclusive scan over g_cur -> g_rowptr; also re-zeros g_cur
__global__ void scan_k() {
    __shared__ int ws[32];
    __shared__ int s_carry;
    int t = threadIdx.x, lane = t & 31, wid = t >> 5;
    if (t == 0) s_carry = 0;
    __syncthreads();
    for (int base = 0; base < NN; base += 1024) {
        int i = base + t;
        int v = (i < NN) ? g_cur[i] : 0;
        if (i < NN) g_cur[i] = 0;
        int x = v;
        #pragma unroll
        for (int o = 1; o < 32; o <<= 1) {
            int y = __shfl_up_sync(0xffffffffu, x, o);
            if (lane >= o) x += y;
        }
        if (lane == 31) ws[wid] = x;
        __syncthreads();
        if (wid == 0) {
            int y = ws[lane];
            #pragma unroll
            for (int o = 1; o < 32; o <<= 1) {
                int z = __shfl_up_sync(0xffffffffu, y, o);
                if (lane >= o) y += z;
            }
            ws[lane] = y;
        }
        __syncthreads();
        int incl = x + (wid ? ws[wid - 1] : 0);
        int carry = s_carry;
        if (i < NN) g_rowptr[i] = carry + incl - v;
        int total = ws[31];
        __syncthreads();
        if (t == 0) s_carry = carry + total;
        __syncthreads();
    }
    if (t == 0) g_rowptr[NN] = s_carry;
}

__global__ void scatter_k(const int* __restrict__ src, const int* __restrict__ dst) {
    int e = blockIdx.x * blockDim.x + threadIdx.x;
    if (e < EE) {
        int d = dst[e];
        int pos = g_rowptr[d] + atomicAdd(&g_cur[d], 1);
        g_csr[pos] = src[e];
    }
}

// ---------------------------------------------------------------------------
// Weight split: W = Wh + Wl, both tf32 (rna). Kills weight rounding error.
// ---------------------------------------------------------------------------
__global__ void split_w_k(const float* __restrict__ W, int n) {
    int i = blockIdx.x * blockDim.x + threadIdx.x;
    if (i < n) {
        float w = W[i];
        uint32_t hb;
        asm("cvt.rna.tf32.f32 %0, %1;" : "=r"(hb) : "f"(w));
        float wh = __uint_as_float(hb);
        float r = w - wh;
        uint32_t lb;
        asm("cvt.rna.tf32.f32 %0, %1;" : "=r"(lb) : "f"(r));
        g_Wh[i] = wh;
        g_Wl[i] = __uint_as_float(lb);
    }
}

// ---------------------------------------------------------------------------
// tf32 tensor-core GEMM + fused attention coefficients.
// feat[64 x 256] = A[64 x K] @ (Wh+Wl)[K x 256], el/er epilogue.
// Block: 256 thr = 8 warps, 2(M) x 4(N); warp tile m32 x n64 (1 head/warp).
// ---------------------------------------------------------------------------
__device__ __forceinline__ void mma_tf32(float* c, const uint32_t* a,
                                         uint32_t b0, uint32_t b1)
{
    asm volatile(
        "mma.sync.aligned.m16n8k8.row.col.f32.tf32.tf32.f32 "
        "{%0,%1,%2,%3}, {%4,%5,%6,%7}, {%8,%9}, {%0,%1,%2,%3};"
        : "+f"(c[0]), "+f"(c[1]), "+f"(c[2]), "+f"(c[3])
        : "r"(a[0]), "r"(a[1]), "r"(a[2]), "r"(a[3]), "r"(b0), "r"(b1));
}

template <int K>
__global__ void __launch_bounds__(256) gemm_mma_k(
    const float* __restrict__ hin,
    const float* __restrict__ al, const float* __restrict__ ar)
{
    constexpr int AS = K + 4;    // A smem stride (conflict-free)
    constexpr int WS = 264;      // W smem stride (conflict-free)
    constexpr int NCH = K / 32;  // 32-wide k-chunks
    extern __shared__ float sm[];
    float* sA  = sm;                 // 64*AS
    float* sWh = sm + 64 * AS;       // 32*WS
    float* sWl = sWh + 32 * WS;      // 32*WS

    int t = threadIdx.x, lane = t & 31, wid = t >> 5;
    int wm = wid >> 2, wn = wid & 3;     // warp M-row, warp N-col (= head)
    int g = lane >> 2, q = lane & 3;     // groupID (row), quad lane (col)
    int n0 = blockIdx.x * 64;

    // Stage A, tf32-rounded, zero-fill rows >= NN
    for (int idx = t; idx < 64 * K; idx += 256) {
        int r = idx / K, c = idx % K;
        float v = 0.f;
        if (n0 + r < NN) v = hin[(size_t)(n0 + r) * K + c];
        uint32_t vb;
        asm("cvt.rna.tf32.f32 %0, %1;" : "=r"(vb) : "f"(v));
        sA[r * AS + c] = __uint_as_float(vb);
    }

    float c_[2][8][4];
    #pragma unroll
    for (int i = 0; i < 2; i++)
        #pragma unroll
        for (int j = 0; j < 8; j++)
            #pragma unroll
            for (int r = 0; r < 4; r++) c_[i][j][r] = 0.f;

    for (int kc = 0; kc < NCH; kc++) {
        __syncthreads();
        for (int idx = t; idx < 32 * 256; idx += 256) {
            int kk = idx >> 8, n = idx & 255;
            sWh[kk * WS + n] = g_Wh[(kc * 32 + kk) * 256 + n];
            sWl[kk * WS + n] = g_Wl[(kc * 32 + kk) * 256 + n];
        }
        __syncthreads();

        #pragma unroll
        for (int j8 = 0; j8 < 4; j8++) {
            int kcol = kc * 32 + j8 * 8;
            uint32_t a[2][4];
            #pragma unroll
            for (int i = 0; i < 2; i++) {
                int r = wm * 32 + i * 16 + g;
                a[i][0] = __float_as_uint(sA[r * AS + kcol + q]);
                a[i][1] = __float_as_uint(sA[(r + 8) * AS + kcol + q]);
                a[i][2] = __float_as_uint(sA[r * AS + kcol + q + 4]);
                a[i][3] = __float_as_uint(sA[(r + 8) * AS + kcol + q + 4]);
            }
            #pragma unroll
            for (int j = 0; j < 8; j++) {
                int ncol = wn * 64 + j * 8 + g;
                int krow = j8 * 8 + q;
                uint32_t bh0 = __float_as_uint(sWh[krow * WS + ncol]);
                uint32_t bh1 = __float_as_uint(sWh[(krow + 4) * WS + ncol]);
                uint32_t bl0 = __float_as_uint(sWl[krow * WS + ncol]);
                uint32_t bl1 = __float_as_uint(sWl[(krow + 4) * WS + ncol]);
                #pragma unroll
                for (int i = 0; i < 2; i++) {
                    mma_tf32(c_[i][j], a[i], bh0, bh1);
                    mma_tf32(c_[i][j], a[i], bl0, bl1);
                }
            }
        }
    }

    // Epilogue: store feat, fused el/er (this warp's head = wn)
    float alv[8][2], arv[8][2];
    #pragma unroll
    for (int j = 0; j < 8; j++) {
        int col = wn * 64 + j * 8 + 2 * q;
        alv[j][0] = al[col]; alv[j][1] = al[col + 1];
        arv[j][0] = ar[col]; arv[j][1] = ar[col + 1];
    }
    #pragma unroll
    for (int i = 0; i < 2; i++) {
        int rtop = n0 + wm * 32 + i * 16 + g;
        int rbot = rtop + 8;
        float plt = 0.f, prt = 0.f, plb = 0.f, prb = 0.f;
        #pragma unroll
        for (int j = 0; j < 8; j++) {
            int cb = wn * 64 + j * 8 + 2 * q;
            if (rtop < NN)
                *(float2*)&g_feat[(size_t)rtop * HD + cb] =
                    make_float2(c_[i][j][0], c_[i][j][1]);
            if (rbot < NN)
                *(float2*)&g_feat[(size_t)rbot * HD + cb] =
                    make_float2(c_[i][j][2], c_[i][j][3]);
            plt += c_[i][j][0] * alv[j][0] + c_[i][j][1] * alv[j][1];
            prt += c_[i][j][0] * arv[j][0] + c_[i][j][1] * arv[j][1];
            plb += c_[i][j][2] * alv[j][0] + c_[i][j][3] * alv[j][1];
            prb += c_[i][j][2] * arv[j][0] + c_[i][j][3] * arv[j][1];
        }
        #pragma unroll
        for (int o = 1; o <= 2; o <<= 1) {
            plt += __shfl_xor_sync(0xffffffffu, plt, o);
            prt += __shfl_xor_sync(0xffffffffu, prt, o);
            plb += __shfl_xor_sync(0xffffffffu, plb, o);
            prb += __shfl_xor_sync(0xffffffffu, prb, o);
        }
        if (q == 0) {
            if (rtop < NN) { g_el[rtop * HH + wn] = plt; g_er[rtop * HH + wn] = prt; }
            if (rbot < NN) { g_el[rbot * HH + wn] = plb; g_er[rbot * HH + wn] = prb; }
        }
    }
}

// ---------------------------------------------------------------------------
// Edge softmax + weighted aggregation. One block (128 thr) per dst node.
// Softmax: warp h owns head h (1/sum folded into weights).
// Gather: LDG.128 — 64 float4-lanes per edge row, 2 edge slots (p = t>>6),
// unrolled x2 => 4x16B loads in flight per thread.
// ---------------------------------------------------------------------------
template <bool MEAN>
__global__ void __launch_bounds__(128) edge_agg_k(
    const float* __restrict__ b, float* __restrict__ out)
{
    constexpr int MAXDEG = 64;
    int n = blockIdx.x;
    int t = threadIdx.x, lane = t & 31, wh = t >> 5;
    int rb = g_rowptr[n];
    int deg = g_rowptr[n + 1] - rb;

    __shared__ int    s_src[MAXDEG];
    __shared__ float  s_w[HH][MAXDEG + 1];   // +1 pad: head rows in distinct banks
    __shared__ float4 s_acc[64];

    const float4* feat4 = (const float4*)g_feat;
    const float4* b4 = (const float4*)b;

    // -------- rare fallback: deg > MAXDEG (old per-head float2 path) --------
    if (deg > MAXDEG) {
        float er_h = g_er[n * HH + wh];
        float m = -1e30f;
        for (int j = lane; j < deg; j += 32) {
            int sn = g_csr[rb + j];
            float e = g_el[sn * HH + wh] + er_h;
            e = e > 0.f ? e : NEG_SLOPE * e;
            m = fmaxf(m, e);
        }
        #pragma unroll
        for (int o = 16; o; o >>= 1) m = fmaxf(m, __shfl_xor_sync(0xffffffffu, m, o));
        float s = 0.f;
        for (int j = lane; j < deg; j += 32) {
            int sn = g_csr[rb + j];
            float e = g_el[sn * HH + wh] + er_h;
            e = e > 0.f ? e : NEG_SLOPE * e;
            s += __expf(e - m);
        }
        #pragma unroll
        for (int o = 16; o; o >>= 1) s += __shfl_xor_sync(0xffffffffu, s, o);
        float inv = 1.0f / s;
        float2 acc = make_float2(0.f, 0.f);
        const float2* fb = (const float2*)g_feat + (wh * 32 + lane);
        for (int j = 0; j < deg; j++) {
            int sn = g_csr[rb + j];
            float e = g_el[sn * HH + wh] + er_h;
            e = e > 0.f ? e : NEG_SLOPE * e;
            float w = __expf(e - m);
            float2 f = fb[(size_t)sn * 128];
            acc.x += w * f.x; acc.y += w * f.y;
        }
        acc.x *= inv; acc.y *= inv;
        // reuse s_acc as float[4][64]
        float* s_o = (float*)s_acc;
        s_o[wh * 64 + 2 * lane]     = acc.x;
        s_o[wh * 64 + 2 * lane + 1] = acc.y;
        __syncthreads();
        if (MEAN) {
            if (t < DD) {
                float v = 0.25f * (s_o[t] + s_o[64 + t] + s_o[128 + t] + s_o[192 + t])
                        + 0.25f * (b[t] + b[DD + t] + b[2 * DD + t] + b[3 * DD + t]);
                out[(size_t)n * DD + t] = v;
            }
        } else {
            int o = wh * DD + 2 * lane;
            out[(size_t)n * HD + o]     = acc.x + b[o];
            out[(size_t)n * HD + o + 1] = acc.y + b[o + 1];
        }
        return;
    }

    float4 acc4 = make_float4(0.f, 0.f, 0.f, 0.f);
    int c = t & 63;          // float4 lane within feature row
    int p = t >> 6;          // edge slot (0/1)
    int h = c >> 4;          // head owning this lane's features

    if (deg > 0) {
        // stage edges: leaky_relu(el[src] + er[dst]) per head
        float4 er4 = *(const float4*)(g_er + n * HH);
        if (t < deg) {
            int sn = g_csr[rb + t];
            s_src[t] = sn;
            float4 el4 = *(const float4*)(g_el + sn * HH);
            float e0 = el4.x + er4.x; s_w[0][t] = e0 > 0.f ? e0 : NEG_SLOPE * e0;
            float e1 = el4.y + er4.y; s_w[1][t] = e1 > 0.f ? e1 : NEG_SLOPE * e1;
            float e2 = el4.z + er4.z; s_w[2][t] = e2 > 0.f ? e2 : NEG_SLOPE * e2;
            float e3 = el4.w + er4.w; s_w[3][t] = e3 > 0.f ? e3 : NEG_SLOPE * e3;
        }
        __syncthreads();

        // softmax per head (warp wh owns head wh); fold 1/sum into weights
        float m = -1e30f;
        for (int j = lane; j < deg; j += 32) m = fmaxf(m, s_w[wh][j]);
        #pragma unroll
        for (int o = 16; o; o >>= 1) m = fmaxf(m, __shfl_xor_sync(0xffffffffu, m, o));
        float s = 0.f;
        for (int j = lane; j < deg; j += 32) {
            float w = __expf(s_w[wh][j] - m);
            s_w[wh][j] = w;
            s += w;
        }
        #pragma unroll
        for (int o = 16; o; o >>= 1) s += __shfl_xor_sync(0xffffffffu, s, o);
        float inv = 1.0f / s;
        for (int j = lane; j < deg; j += 32) s_w[wh][j] *= inv;
        __syncthreads();

        // gather: 2 edge slots x unroll 2 => 4 independent LDG.128 chains
        int j = p;
        for (; j + 2 < deg; j += 4) {
            int   s0 = s_src[j],      s1 = s_src[j + 2];
            float w0 = s_w[h][j],     w1 = s_w[h][j + 2];
            float4 f0 = feat4[(size_t)s0 * 64 + c];
            float4 f1 = feat4[(size_t)s1 * 64 + c];
            acc4.x += w0 * f0.x + w1 * f1.x;
            acc4.y += w0 * f0.y + w1 * f1.y;
            acc4.z += w0 * f0.z + w1 * f1.z;
            acc4.w += w0 * f0.w + w1 * f1.w;
        }
        for (; j < deg; j += 2) {
            int   s0 = s_src[j];
            float w0 = s_w[h][j];
            float4 f0 = feat4[(size_t)s0 * 64 + c];
            acc4.x += w0 * f0.x;
            acc4.y += w0 * f0.y;
            acc4.z += w0 * f0.z;
            acc4.w += w0 * f0.w;
        }
        __syncthreads();   // s_acc reuse barrier (s_w region distinct, but keep order)
    }

    // combine the two edge slots
    if (p == 1) s_acc[c] = acc4;
    __syncthreads();
    if (p == 0) {
        float4 o4 = s_acc[c];
        acc4.x += o4.x; acc4.y += o4.y; acc4.z += o4.z; acc4.w += o4.w;
    }

    if (MEAN) {
        if (p == 0) s_acc[c] = acc4;
        __syncthreads();
        if (t < 16) {
            float4 v0 = s_acc[t], v1 = s_acc[t + 16];
            float4 v2 = s_acc[t + 32], v3 = s_acc[t + 48];
            float4 bb0 = b4[t], bb1 = b4[t + 16], bb2 = b4[t + 32], bb3 = b4[t + 48];
            float4 r;
            r.x = 0.25f * (v0.x + v1.x + v2.x + v3.x + bb0.x + bb1.x + bb2.x + bb3.x);
            r.y = 0.25f * (v0.y + v1.y + v2.y + v3.y + bb0.y + bb1.y + bb2.y + bb3.y);
            r.z = 0.25f * (v0.z + v1.z + v2.z + v3.z + bb0.z + bb1.z + bb2.z + bb3.z);
            r.w = 0.25f * (v0.w + v1.w + v2.w + v3.w + bb0.w + bb1.w + bb2.w + bb3.w);
            *(float4*)(out + (size_t)n * DD + t * 4) = r;
        }
    } else {
        if (p == 0) {
            float4 bb = b4[c];
            float4 r;
            r.x = acc4.x + bb.x; r.y = acc4.y + bb.y;
            r.z = acc4.z + bb.z; r.w = acc4.w + bb.w;
            *(float4*)(out + (size_t)n * HD + c * 4) = r;
        }
    }
}

// ---------------------------------------------------------------------------
// Final Linear(256->64) + LayerNorm (no affine). 16 nodes/block, 64 threads.
// ---------------------------------------------------------------------------
__global__ void __launch_bounds__(64) final_ln_k(
    const float* __restrict__ hin, const float* __restrict__ Wo,
    const float* __restrict__ bo, float* __restrict__ out)
{
    constexpr int NB = 16;
    constexpr int K4 = HD / 4;               // 64
    __shared__ float4 sh4[NB * K4];          // 16 KB
    __shared__ float so[NB * DD];            // 4 KB
    __shared__ float mu_s[NB], rs_s[NB];
    int t = threadIdx.x;
    int n0 = blockIdx.x * NB;

    const float4* hin4 = (const float4*)(hin + (size_t)n0 * HD);
    for (int idx = t; idx < NB * K4; idx += 64)
        sh4[idx] = hin4[idx];
    __syncthreads();

    float acc[NB];
    #pragma unroll
    for (int i = 0; i < NB; i++) acc[i] = 0.f;
    float bv = bo[t];

    for (int k4 = 0; k4 < K4; k4++) {
        int k = k4 * 4;
        float w0 = __ldg(&Wo[(k + 0) * DD + t]);
        float w1 = __ldg(&Wo[(k + 1) * DD + t]);
        float w2 = __ldg(&Wo[(k + 2) * DD + t]);
        float w3 = __ldg(&Wo[(k + 3) * DD + t]);
        #pragma unroll
        for (int i = 0; i < NB; i++) {
            float4 s = sh4[i * K4 + k4];
            acc[i] += s.x * w0;
            acc[i] += s.y * w1;
            acc[i] += s.z * w2;
            acc[i] += s.w * w3;
        }
    }

    #pragma unroll
    for (int i = 0; i < NB; i++) so[i * DD + t] = acc[i] + bv;
    __syncthreads();

    if (t < NB) {
        float s = 0.f;
        for (int j = 0; j < DD; j++) s += so[t * DD + j];
        float mu = s * (1.0f / DD);
        float s2 = 0.f;
        for (int j = 0; j < DD; j++) {
            float d = so[t * DD + j] - mu;
            s2 += d * d;
        }
        mu_s[t] = mu;
        rs_s[t] = rsqrtf(s2 * (1.0f / DD) + 1e-5f);
    }
    __syncthreads();

    #pragma unroll
    for (int i = 0; i < NB; i++)
        out[(size_t)(n0 + i) * DD + t] = (so[i * DD + t] - mu_s[i]) * rs_s[i];
}

// ---------------------------------------------------------------------------
// Launch: inputs (metadata order):
// 0 in_feat[N,128] 1 src[E] 2 dst[E] 3 W1[128,256] 4 al1[4,64] 5 ar1[4,64]
// 6 b1[256] 7 Wh[3,64,256] 8 alh[3,4,64] 9 arh[3,4,64] 10 bh[3,256]
// 11 Wo[256,64] 12 bo[64]  -> out float32 [N,64]
// ---------------------------------------------------------------------------
extern "C" void kernel_launch(void* const* d_in, const int* in_sizes, int n_in,
                              void* d_out, int out_size)
{
    const float* in_feat = (const float*)d_in[0];
    const int*   src     = (const int*)d_in[1];
    const int*   dst     = (const int*)d_in[2];
    const float* W1      = (const float*)d_in[3];
    const float* al1     = (const float*)d_in[4];
    const float* ar1     = (const float*)d_in[5];
    const float* b1      = (const float*)d_in[6];
    const float* Whp     = (const float*)d_in[7];
    const float* alh     = (const float*)d_in[8];
    const float* arh     = (const float*)d_in[9];
    const float* bh      = (const float*)d_in[10];
    const float* Wo      = (const float*)d_in[11];
    const float* bo      = (const float*)d_in[12];
    float* out = (float*)d_out;

    float* g_h_ptr;
    cudaGetSymbolAddress((void**)&g_h_ptr, g_h);

    const int SMEM1 = (64 * (IN_F + 4) + 2 * 32 * 264) * 4;   // 101376 B
    const int SMEMH = (64 * (DD + 4) + 2 * 32 * 264) * 4;     //  84992 B
    cudaFuncSetAttribute(gemm_mma_k<IN_F>,
                         cudaFuncAttributeMaxDynamicSharedMemorySize, SMEM1);
    cudaFuncSetAttribute(gemm_mma_k<DD>,
                         cudaFuncAttributeMaxDynamicSharedMemorySize, SMEMH);

    // CSR build
    zero_cur_k<<<(NN + 255) / 256, 256>>>();
    hist_k<<<(EE + 255) / 256, 256>>>(dst);
    scan_k<<<1, 1024>>>();
    scatter_k<<<(EE + 255) / 256, 256>>>(src, dst);

    const int GMMA = (NN + 63) / 64;   // 782 blocks

    // Layer 1: conv1 (K=128), mean over heads -> g_h[N,64]
    split_w_k<<<(IN_F * HD + 255) / 256, 256>>>(W1, IN_F * HD);
    gemm_mma_k<IN_F><<<GMMA, 256, SMEM1>>>(in_feat, al1, ar1);
    edge_agg_k<true><<<NN, 128>>>(b1, g_h_ptr);

    // Hidden layers 0,1 (mean)
    for (int l = 0; l < 2; l++) {
        split_w_k<<<(DD * HD + 255) / 256, 256>>>(Whp + (size_t)l * DD * HD, DD * HD);
        gemm_mma_k<DD><<<GMMA, 256, SMEMH>>>(g_h_ptr, alh + l * HD, arh + l * HD);
        edge_agg_k<true><<<NN, 128>>>(bh + l * HD, g_h_ptr);
    }

    // Hidden layer 2 (full [N,H,D] output)
    split_w_k<<<(DD * HD + 255) / 256, 256>>>(Whp + (size_t)2 * DD * HD, DD * HD);
    gemm_mma_k<DD><<<GMMA, 256, SMEMH>>>(g_h_ptr, alh + 2 * HD, arh + 2 * HD);
    edge_agg_k<false><<<NN, 128>>>(bh + 2 * HD, g_h_ptr);

    // Final linear + LayerNorm -> d_out
    final_ln_k<<<NN / 16, 64>>>(g_h_ptr, Wo, bo, out);
}

// round 5
// speedup vs baseline: 1.0747x; 1.0747x over previous
#include <cuda_runtime.h>
#include <cuda_bf16.h>
#include <cstdint>

// Problem constants (match reference_code)
#define NN 50000      // nodes
#define EE 800000     // edges
#define IN_F 128
#define DD 64
#define HH 4
#define HD 256        // H*D
#define NEG_SLOPE 0.2f

// ---------------------------------------------------------------------------
// Scratch (static __device__ arrays — no allocation allowed)
// ---------------------------------------------------------------------------
__device__ float    g_feat[(size_t)NN * HD];   // projected features [N,256]
__device__ float    g_h[(size_t)NN * HD];      // layer io buffer
__device__ float    g_el[(size_t)NN * HH];
__device__ float    g_er[(size_t)NN * HH];
__device__ int      g_rowptr[NN + 1];
__device__ int      g_cur[NN];
__device__ int      g_csr[EE];                 // src per CSR slot (sorted by dst)
__device__ uint32_t g_Wph[(IN_F / 2) * HD];    // W bf16-high, k-pairs packed
__device__ uint32_t g_Wpl[(IN_F / 2) * HD];    // W bf16-low,  k-pairs packed

// ---------------------------------------------------------------------------
// CSR build: zero -> histogram(dst) -> scan -> scatter
// ---------------------------------------------------------------------------
__global__ void zero_cur_k() {
    int i = blockIdx.x * blockDim.x + threadIdx.x;
    if (i < NN) g_cur[i] = 0;
}

__global__ void hist_k(const int* __restrict__ dst) {
    int e = blockIdx.x * blockDim.x + threadIdx.x;
    if (e < EE) atomicAdd(&g_cur[dst[e]], 1);
}

// single-block exclusive scan over g_cur -> g_rowptr; also re-zeros g_cur
__global__ void scan_k() {
    __shared__ int ws[32];
    __shared__ int s_carry;
    int t = threadIdx.x, lane = t & 31, wid = t >> 5;
    if (t == 0) s_carry = 0;
    __syncthreads();
    for (int base = 0; base < NN; base += 1024) {
        int i = base + t;
        int v = (i < NN) ? g_cur[i] : 0;
        if (i < NN) g_cur[i] = 0;
        int x = v;
        #pragma unroll
        for (int o = 1; o < 32; o <<= 1) {
            int y = __shfl_up_sync(0xffffffffu, x, o);
            if (lane >= o) x += y;
        }
        if (lane == 31) ws[wid] = x;
        __syncthreads();
        if (wid == 0) {
            int y = ws[lane];
            #pragma unroll
            for (int o = 1; o < 32; o <<= 1) {
                int z = __shfl_up_sync(0xffffffffu, y, o);
                if (lane >= o) y += z;
            }
            ws[lane] = y;
        }
        __syncthreads();
        int incl = x + (wid ? ws[wid - 1] : 0);
        int carry = s_carry;
        if (i < NN) g_rowptr[i] = carry + incl - v;
        int total = ws[31];
        __syncthreads();
        if (t == 0) s_carry = carry + total;
        __syncthreads();
    }
    if (t == 0) g_rowptr[NN] = s_carry;
}

__global__ void scatter_k(const int* __restrict__ src, const int* __restrict__ dst) {
    int e = blockIdx.x * blockDim.x + threadIdx.x;
    if (e < EE) {
        int d = dst[e];
        int pos = g_rowptr[d] + atomicAdd(&g_cur[d], 1);
        g_csr[pos] = src[e];
    }
}

// ---------------------------------------------------------------------------
// bf16 split helpers
// ---------------------------------------------------------------------------
__device__ __forceinline__ void bf16_split(float v, __nv_bfloat16& h, __nv_bfloat16& l) {
    h = __float2bfloat16_rn(v);
    l = __float2bfloat16_rn(v - __bfloat162float(h));
}
__device__ __forceinline__ uint32_t pack_bf16(__nv_bfloat16 lo, __nv_bfloat16 hi) {
    __nv_bfloat162 p = __halves2bfloat162(lo, hi);
    return *reinterpret_cast<uint32_t*>(&p);
}

// Split W[K x 256] into packed bf16 hi/lo with k-pairs in one uint32.
__global__ void split_w_k(const float* __restrict__ W, int k2n) {
    int idx = blockIdx.x * blockDim.x + threadIdx.x;
    if (idx < k2n) {
        int k2 = idx >> 8, n = idx & 255;
        float w0 = W[(2 * k2) * 256 + n];
        float w1 = W[(2 * k2 + 1) * 256 + n];
        __nv_bfloat16 h0, l0, h1, l1;
        bf16_split(w0, h0, l0);
        bf16_split(w1, h1, l1);
        g_Wph[idx] = pack_bf16(h0, h1);
        g_Wpl[idx] = pack_bf16(l0, l1);
    }
}

// ---------------------------------------------------------------------------
// bf16 3-term tensor-core GEMM + fused attention coefficients.
// feat[64 x 256] = A[64 x K] @ W[K x 256],  A=Ah+Al, W=Wh+Wl (bf16 splits),
// D = Ah*Wh + Ah*Wl + Al*Wh  (Al*Wl ~ 4e-6, dropped).
// Block: 256 thr = 8 warps, 2(M) x 4(N); warp tile m32 x n64 (1 head/warp).
// ---------------------------------------------------------------------------
__device__ __forceinline__ void mma_bf16(float* c, const uint32_t* a,
                                         uint32_t b0, uint32_t b1)
{
    asm volatile(
        "mma.sync.aligned.m16n8k16.row.col.f32.bf16.bf16.f32 "
        "{%0,%1,%2,%3}, {%4,%5,%6,%7}, {%8,%9}, {%0,%1,%2,%3};"
        : "+f"(c[0]), "+f"(c[1]), "+f"(c[2]), "+f"(c[3])
        : "r"(a[0]), "r"(a[1]), "r"(a[2]), "r"(a[3]), "r"(b0), "r"(b1));
}

template <int K>
__global__ void __launch_bounds__(256) gemm_mma_k(
    const float* __restrict__ hin,
    const float* __restrict__ al, const float* __restrict__ ar)
{
    constexpr int K2  = K / 2;
    constexpr int ASp = K2 + 4;   // ≡ 4 (mod 32): A frag loads conflict-free
    constexpr int WSp = 264;      // ≡ 8 (mod 32): B frag loads conflict-free
    extern __shared__ uint32_t smu[];
    uint32_t* sAh = smu;                         // 64*ASp
    uint32_t* sAl = sAh + 64 * ASp;              // 64*ASp
    uint32_t* sWh = sAl + 64 * ASp;              // K2*WSp
    uint32_t* sWl = sWh + K2 * WSp;              // K2*WSp

    int t = threadIdx.x, lane = t & 31, wid = t >> 5;
    int wm = wid >> 2, wn = wid & 3;     // warp M-row, warp N-col (= head)
    int g = lane >> 2, q = lane & 3;     // groupID (row), quad lane
    int n0 = blockIdx.x * 64;

    // Stage A as packed bf16 hi/lo k-pairs; zero-fill rows >= NN
    for (int idx = t; idx < 64 * K2; idx += 256) {
        int r = idx / K2, k2 = idx % K2;
        float v0 = 0.f, v1 = 0.f;
        if (n0 + r < NN) {
            float2 vv = *(const float2*)&hin[(size_t)(n0 + r) * K + 2 * k2];
            v0 = vv.x; v1 = vv.y;
        }
        __nv_bfloat16 h0, l0, h1, l1;
        bf16_split(v0, h0, l0);
        bf16_split(v1, h1, l1);
        sAh[r * ASp + k2] = pack_bf16(h0, h1);
        sAl[r * ASp + k2] = pack_bf16(l0, l1);
    }
    // Stage full W (hi/lo)
    for (int idx = t; idx < K2 * 256; idx += 256) {
        int k2 = idx >> 8, n = idx & 255;
        sWh[k2 * WSp + n] = g_Wph[idx];
        sWl[k2 * WSp + n] = g_Wpl[idx];
    }
    __syncthreads();

    float c_[2][8][4];
    #pragma unroll
    for (int i = 0; i < 2; i++)
        #pragma unroll
        for (int j = 0; j < 8; j++)
            #pragma unroll
            for (int r = 0; r < 4; r++) c_[i][j][r] = 0.f;

    for (int ks = 0; ks < K / 16; ks++) {
        int k2b = ks * 8;
        uint32_t ah[2][4], alr[2][4];
        #pragma unroll
        for (int i = 0; i < 2; i++) {
            int r = wm * 32 + i * 16 + g;
            ah[i][0]  = sAh[r * ASp + k2b + q];
            ah[i][1]  = sAh[(r + 8) * ASp + k2b + q];
            ah[i][2]  = sAh[r * ASp + k2b + 4 + q];
            ah[i][3]  = sAh[(r + 8) * ASp + k2b + 4 + q];
            alr[i][0] = sAl[r * ASp + k2b + q];
            alr[i][1] = sAl[(r + 8) * ASp + k2b + q];
            alr[i][2] = sAl[r * ASp + k2b + 4 + q];
            alr[i][3] = sAl[(r + 8) * ASp + k2b + 4 + q];
        }
        #pragma unroll
        for (int j = 0; j < 8; j++) {
            int ncol = wn * 64 + j * 8 + g;
            uint32_t bh0 = sWh[(k2b + q) * WSp + ncol];
            uint32_t bh1 = sWh[(k2b + 4 + q) * WSp + ncol];
            uint32_t bl0 = sWl[(k2b + q) * WSp + ncol];
            uint32_t bl1 = sWl[(k2b + 4 + q) * WSp + ncol];
            #pragma unroll
            for (int i = 0; i < 2; i++) {
                mma_bf16(c_[i][j], ah[i], bh0, bh1);
                mma_bf16(c_[i][j], ah[i], bl0, bl1);
                mma_bf16(c_[i][j], alr[i], bh0, bh1);
            }
        }
    }

    // Epilogue: store feat, fused el/er (this warp's head = wn)
    float alv[8][2], arv[8][2];
    #pragma unroll
    for (int j = 0; j < 8; j++) {
        int col = wn * 64 + j * 8 + 2 * q;
        alv[j][0] = al[col]; alv[j][1] = al[col + 1];
        arv[j][0] = ar[col]; arv[j][1] = ar[col + 1];
    }
    #pragma unroll
    for (int i = 0; i < 2; i++) {
        int rtop = n0 + wm * 32 + i * 16 + g;
        int rbot = rtop + 8;
        float plt = 0.f, prt = 0.f, plb = 0.f, prb = 0.f;
        #pragma unroll
        for (int j = 0; j < 8; j++) {
            int cb = wn * 64 + j * 8 + 2 * q;
            if (rtop < NN)
                *(float2*)&g_feat[(size_t)rtop * HD + cb] =
                    make_float2(c_[i][j][0], c_[i][j][1]);
            if (rbot < NN)
                *(float2*)&g_feat[(size_t)rbot * HD + cb] =
                    make_float2(c_[i][j][2], c_[i][j][3]);
            plt += c_[i][j][0] * alv[j][0] + c_[i][j][1] * alv[j][1];
            prt += c_[i][j][0] * arv[j][0] + c_[i][j][1] * arv[j][1];
            plb += c_[i][j][2] * alv[j][0] + c_[i][j][3] * alv[j][1];
            prb += c_[i][j][2] * arv[j][0] + c_[i][j][3] * arv[j][1];
        }
        #pragma unroll
        for (int o = 1; o <= 2; o <<= 1) {
            plt += __shfl_xor_sync(0xffffffffu, plt, o);
            prt += __shfl_xor_sync(0xffffffffu, prt, o);
            plb += __shfl_xor_sync(0xffffffffu, plb, o);
            prb += __shfl_xor_sync(0xffffffffu, prb, o);
        }
        if (q == 0) {
            if (rtop < NN) { g_el[rtop * HH + wn] = plt; g_er[rtop * HH + wn] = prt; }
            if (rbot < NN) { g_el[rbot * HH + wn] = plb; g_er[rbot * HH + wn] = prb; }
        }
    }
}

// ---------------------------------------------------------------------------
// Edge softmax + weighted aggregation (R3 version — best measured).
// One block (128 thr) per dst node, warp h handles head h. CSR gather,
// no atomics, gather loop unrolled x4.
// ---------------------------------------------------------------------------
template <bool MEAN>
__global__ void __launch_bounds__(128) edge_agg_k(
    const float* __restrict__ b, float* __restrict__ out)
{
    constexpr int MAXDEG = 64;
    int n = blockIdx.x;
    int t = threadIdx.x, lane = t & 31, h = t >> 5;
    int rb = g_rowptr[n];
    int deg = g_rowptr[n + 1] - rb;

    __shared__ int   s_src[MAXDEG];
    __shared__ float s_w[HH][MAXDEG];
    __shared__ float s_out[HH][DD];

    float2 acc = make_float2(0.f, 0.f);
    const float2* fb = (const float2*)g_feat + (h * 32 + lane);

    if (deg > 0 && deg <= MAXDEG) {
        float4 er4 = *(const float4*)(g_er + n * HH);
        if (t < MAXDEG && t < deg) {
            int j = t;
            int sn = g_csr[rb + j];
            s_src[j] = sn;
            float4 el4 = *(const float4*)(g_el + sn * HH);
            float e0 = el4.x + er4.x; s_w[0][j] = e0 > 0.f ? e0 : NEG_SLOPE * e0;
            float e1 = el4.y + er4.y; s_w[1][j] = e1 > 0.f ? e1 : NEG_SLOPE * e1;
            float e2 = el4.z + er4.z; s_w[2][j] = e2 > 0.f ? e2 : NEG_SLOPE * e2;
            float e3 = el4.w + er4.w; s_w[3][j] = e3 > 0.f ? e3 : NEG_SLOPE * e3;
        }
        __syncthreads();

        float m = -1e30f;
        for (int j = lane; j < deg; j += 32) m = fmaxf(m, s_w[h][j]);
        #pragma unroll
        for (int o = 16; o; o >>= 1) m = fmaxf(m, __shfl_xor_sync(0xffffffffu, m, o));
        float s = 0.f;
        for (int j = lane; j < deg; j += 32) {
            float w = __expf(s_w[h][j] - m);
            s_w[h][j] = w;
            s += w;
        }
        #pragma unroll
        for (int o = 16; o; o >>= 1) s += __shfl_xor_sync(0xffffffffu, s, o);
        float inv = 1.0f / s;
        __syncwarp();

        int j = 0;
        for (; j + 4 <= deg; j += 4) {
            int   s0 = s_src[j],     s1 = s_src[j + 1];
            int   s2 = s_src[j + 2], s3 = s_src[j + 3];
            float w0 = s_w[h][j],     w1 = s_w[h][j + 1];
            float w2 = s_w[h][j + 2], w3 = s_w[h][j + 3];
            float2 f0 = fb[(size_t)s0 * 128];
            float2 f1 = fb[(size_t)s1 * 128];
            float2 f2 = fb[(size_t)s2 * 128];
            float2 f3 = fb[(size_t)s3 * 128];
            acc.x += w0 * f0.x; acc.y += w0 * f0.y;
            acc.x += w1 * f1.x; acc.y += w1 * f1.y;
            acc.x += w2 * f2.x; acc.y += w2 * f2.y;
            acc.x += w3 * f3.x; acc.y += w3 * f3.y;
        }
        for (; j < deg; j++) {
            float w = s_w[h][j];
            float2 f = fb[(size_t)s_src[j] * 128];
            acc.x += w * f.x; acc.y += w * f.y;
        }
        acc.x *= inv; acc.y *= inv;
    } else if (deg > MAXDEG) {
        float er_h = g_er[n * HH + h];
        float m = -1e30f;
        for (int j = lane; j < deg; j += 32) {
            int sn = g_csr[rb + j];
            float e = g_el[sn * HH + h] + er_h;
            e = e > 0.f ? e : NEG_SLOPE * e;
            m = fmaxf(m, e);
        }
        #pragma unroll
        for (int o = 16; o; o >>= 1) m = fmaxf(m, __shfl_xor_sync(0xffffffffu, m, o));
        float s = 0.f;
        for (int j = lane; j < deg; j += 32) {
            int sn = g_csr[rb + j];
            float e = g_el[sn * HH + h] + er_h;
            e = e > 0.f ? e : NEG_SLOPE * e;
            s += __expf(e - m);
        }
        #pragma unroll
        for (int o = 16; o; o >>= 1) s += __shfl_xor_sync(0xffffffffu, s, o);
        float inv = 1.0f / s;
        for (int j = 0; j < deg; j++) {
            int sn = g_csr[rb + j];
            float e = g_el[sn * HH + h] + er_h;
            e = e > 0.f ? e : NEG_SLOPE * e;
            float w = __expf(e - m);
            float2 f = fb[(size_t)sn * 128];
            acc.x += w * f.x; acc.y += w * f.y;
        }
        acc.x *= inv; acc.y *= inv;
    }

    if (MEAN) {
        s_out[h][2 * lane]     = acc.x;
        s_out[h][2 * lane + 1] = acc.y;
        __syncthreads();
        if (t < DD) {
            float v = 0.25f * (s_out[0][t] + s_out[1][t] + s_out[2][t] + s_out[3][t])
                    + 0.25f * (b[t] + b[DD + t] + b[2 * DD + t] + b[3 * DD + t]);
            out[(size_t)n * DD + t] = v;
        }
    } else {
        int o = h * DD + 2 * lane;
        float2 bb = *(const float2*)(b + o);
        float2 r;
        r.x = acc.x + bb.x;
        r.y = acc.y + bb.y;
        *(float2*)(out + (size_t)n * HD + o) = r;
    }
}

// ---------------------------------------------------------------------------
// Final Linear(256->64) + LayerNorm (no affine). 16 nodes/block, 64 threads.
// ---------------------------------------------------------------------------
__global__ void __launch_bounds__(64) final_ln_k(
    const float* __restrict__ hin, const float* __restrict__ Wo,
    const float* __restrict__ bo, float* __restrict__ out)
{
    constexpr int NB = 16;
    constexpr int K4 = HD / 4;               // 64
    __shared__ float4 sh4[NB * K4];          // 16 KB
    __shared__ float so[NB * DD];            // 4 KB
    __shared__ float mu_s[NB], rs_s[NB];
    int t = threadIdx.x;
    int n0 = blockIdx.x * NB;

    const float4* hin4 = (const float4*)(hin + (size_t)n0 * HD);
    for (int idx = t; idx < NB * K4; idx += 64)
        sh4[idx] = hin4[idx];
    __syncthreads();

    float acc[NB];
    #pragma unroll
    for (int i = 0; i < NB; i++) acc[i] = 0.f;
    float bv = bo[t];

    for (int k4 = 0; k4 < K4; k4++) {
        int k = k4 * 4;
        float w0 = __ldg(&Wo[(k + 0) * DD + t]);
        float w1 = __ldg(&Wo[(k + 1) * DD + t]);
        float w2 = __ldg(&Wo[(k + 2) * DD + t]);
        float w3 = __ldg(&Wo[(k + 3) * DD + t]);
        #pragma unroll
        for (int i = 0; i < NB; i++) {
            float4 s = sh4[i * K4 + k4];
            acc[i] += s.x * w0;
            acc[i] += s.y * w1;
            acc[i] += s.z * w2;
            acc[i] += s.w * w3;
        }
    }

    #pragma unroll
    for (int i = 0; i < NB; i++) so[i * DD + t] = acc[i] + bv;
    __syncthreads();

    if (t < NB) {
        float s = 0.f;
        for (int j = 0; j < DD; j++) s += so[t * DD + j];
        float mu = s * (1.0f / DD);
        float s2 = 0.f;
        for (int j = 0; j < DD; j++) {
            float d = so[t * DD + j] - mu;
            s2 += d * d;
        }
        mu_s[t] = mu;
        rs_s[t] = rsqrtf(s2 * (1.0f / DD) + 1e-5f);
    }
    __syncthreads();

    #pragma unroll
    for (int i = 0; i < NB; i++)
        out[(size_t)(n0 + i) * DD + t] = (so[i * DD + t] - mu_s[i]) * rs_s[i];
}

// ---------------------------------------------------------------------------
// Launch: inputs (metadata order):
// 0 in_feat[N,128] 1 src[E] 2 dst[E] 3 W1[128,256] 4 al1[4,64] 5 ar1[4,64]
// 6 b1[256] 7 Wh[3,64,256] 8 alh[3,4,64] 9 arh[3,4,64] 10 bh[3,256]
// 11 Wo[256,64] 12 bo[64]  -> out float32 [N,64]
// ---------------------------------------------------------------------------
extern "C" void kernel_launch(void* const* d_in, const int* in_sizes, int n_in,
                              void* d_out, int out_size)
{
    const float* in_feat = (const float*)d_in[0];
    const int*   src     = (const int*)d_in[1];
    const int*   dst     = (const int*)d_in[2];
    const float* W1      = (const float*)d_in[3];
    const float* al1     = (const float*)d_in[4];
    const float* ar1     = (const float*)d_in[5];
    const float* b1      = (const float*)d_in[6];
    const float* Whp     = (const float*)d_in[7];
    const float* alh     = (const float*)d_in[8];
    const float* arh     = (const float*)d_in[9];
    const float* bh      = (const float*)d_in[10];
    const float* Wo      = (const float*)d_in[11];
    const float* bo      = (const float*)d_in[12];
    float* out = (float*)d_out;

    float* g_h_ptr;
    cudaGetSymbolAddress((void**)&g_h_ptr, g_h);

    // smem: 2*64*ASp + 2*K2*WSp uint32
    const int SMEM1 = (2 * 64 * (IN_F / 2 + 4) + 2 * (IN_F / 2) * 264) * 4; // 169984
    const int SMEMH = (2 * 64 * (DD / 2 + 4) + 2 * (DD / 2) * 264) * 4;     //  86016
    cudaFuncSetAttribute(gemm_mma_k<IN_F>,
                         cudaFuncAttributeMaxDynamicSharedMemorySize, SMEM1);
    cudaFuncSetAttribute(gemm_mma_k<DD>,
                         cudaFuncAttributeMaxDynamicSharedMemorySize, SMEMH);

    // CSR build
    zero_cur_k<<<(NN + 255) / 256, 256>>>();
    hist_k<<<(EE + 255) / 256, 256>>>(dst);
    scan_k<<<1, 1024>>>();
    scatter_k<<<(EE + 255) / 256, 256>>>(src, dst);

    const int GMMA = (NN + 63) / 64;   // 782 blocks

    // Layer 1: conv1 (K=128), mean over heads -> g_h[N,64]
    split_w_k<<<((IN_F / 2) * HD + 255) / 256, 256>>>(W1, (IN_F / 2) * HD);
    gemm_mma_k<IN_F><<<GMMA, 256, SMEM1>>>(in_feat, al1, ar1);
    edge_agg_k<true><<<NN, 128>>>(b1, g_h_ptr);

    // Hidden layers 0,1 (mean)
    for (int l = 0; l < 2; l++) {
        split_w_k<<<((DD / 2) * HD + 255) / 256, 256>>>(Whp + (size_t)l * DD * HD,
                                                        (DD / 2) * HD);
        gemm_mma_k<DD><<<GMMA, 256, SMEMH>>>(g_h_ptr, alh + l * HD, arh + l * HD);
        edge_agg_k<true><<<NN, 128>>>(bh + l * HD, g_h_ptr);
    }

    // Hidden layer 2 (full [N,H,D] output)
    split_w_k<<<((DD / 2) * HD + 255) / 256, 256>>>(Whp + (size_t)2 * DD * HD,
                                                    (DD / 2) * HD);
    gemm_mma_k<DD><<<GMMA, 256, SMEMH>>>(g_h_ptr, alh + 2 * HD, arh + 2 * HD);
    edge_agg_k<false><<<NN, 128>>>(bh + 2 * HD, g_h_ptr);

    // Final linear + LayerNorm -> d_out
    final_ln_k<<<NN / 16, 64>>>(g_h_ptr, Wo, bo, out);
}

// round 7
// speedup vs baseline: 1.1936x; 1.1106x over previous
#include <cuda_runtime.h>
#include <cuda_bf16.h>
#include <cuda_fp16.h>
#include <cstdint>

// Problem constants (match reference_code)
#define NN 50000      // nodes
#define EE 800000     // edges
#define IN_F 128
#define DD 64
#define HH 4
#define HD 256        // H*D
#define NEG_SLOPE 0.2f

// ---------------------------------------------------------------------------
// Scratch (static __device__ arrays — no allocation allowed)
// ---------------------------------------------------------------------------
__device__ __half   g_feat_h[(size_t)NN * HD]; // projected features [N,256] fp16
__device__ float    g_h[(size_t)NN * HD];      // layer io buffer (fp32)
__device__ float    g_el[(size_t)NN * HH];
__device__ float    g_er[(size_t)NN * HH];
__device__ int      g_rowptr[NN + 1];
__device__ int      g_cur[NN];
__device__ int      g_csr[EE];                 // src per CSR slot (sorted by dst)
__device__ uint32_t g_Wph[(IN_F / 2) * HD];    // W bf16-high, k-pairs packed
__device__ uint32_t g_Wpl[(IN_F / 2) * HD];    // W bf16-low,  k-pairs packed

// ---------------------------------------------------------------------------
// CSR build: zero -> histogram(dst) -> scan -> scatter
// ---------------------------------------------------------------------------
__global__ void zero_cur_k() {
    int i = blockIdx.x * blockDim.x + threadIdx.x;
    if (i < NN) g_cur[i] = 0;
}

__global__ void hist_k(const int* __restrict__ dst) {
    int e = blockIdx.x * blockDim.x + threadIdx.x;
    if (e < EE) atomicAdd(&g_cur[dst[e]], 1);
}

// single-block exclusive scan over g_cur -> g_rowptr; 4 elems/thread/iter.
// Also re-zeros g_cur. NN % 4 == 0.
__global__ void scan_k() {
    __shared__ int ws[32];
    __shared__ int s_carry;
    int t = threadIdx.x, lane = t & 31, wid = t >> 5;
    if (t == 0) s_carry = 0;
    __syncthreads();
    for (int base = 0; base < NN; base += 4096) {
        int i0 = base + t * 4;
        int4 v = make_int4(0, 0, 0, 0);
        if (i0 < NN) {
            v = *(const int4*)&g_cur[i0];
            *(int4*)&g_cur[i0] = make_int4(0, 0, 0, 0);
        }
        int tsum = v.x + v.y + v.z + v.w;
        int x = tsum;
        #pragma unroll
        for (int o = 1; o < 32; o <<= 1) {
            int y = __shfl_up_sync(0xffffffffu, x, o);
            if (lane >= o) x += y;
        }
        if (lane == 31) ws[wid] = x;
        __syncthreads();
        if (wid == 0) {
            int y = ws[lane];
            #pragma unroll
            for (int o = 1; o < 32; o <<= 1) {
                int z = __shfl_up_sync(0xffffffffu, y, o);
                if (lane >= o) y += z;
            }
            ws[lane] = y;
        }
        __syncthreads();
        int excl = x - tsum + (wid ? ws[wid - 1] : 0) + s_carry;
        if (i0 < NN) {
            g_rowptr[i0]     = excl;
            g_rowptr[i0 + 1] = excl + v.x;
            g_rowptr[i0 + 2] = excl + v.x + v.y;
            g_rowptr[i0 + 3] = excl + v.x + v.y + v.z;
        }
        int total = ws[31];
        __syncthreads();
        if (t == 0) s_carry += total;
        __syncthreads();
    }
    if (t == 0) g_rowptr[NN] = s_carry;
}

__global__ void scatter_k(const int* __restrict__ src, const int* __restrict__ dst) {
    int e = blockIdx.x * blockDim.x + threadIdx.x;
    if (e < EE) {
        int d = dst[e];
        int pos = g_rowptr[d] + atomicAdd(&g_cur[d], 1);
        g_csr[pos] = src[e];
    }
}

// ---------------------------------------------------------------------------
// bf16 split helpers
// ---------------------------------------------------------------------------
__device__ __forceinline__ void bf16_split(float v, __nv_bfloat16& h, __nv_bfloat16& l) {
    h = __float2bfloat16_rn(v);
    l = __float2bfloat16_rn(v - __bfloat162float(h));
}
__device__ __forceinline__ uint32_t pack_bf16(__nv_bfloat16 lo, __nv_bfloat16 hi) {
    __nv_bfloat162 p = __halves2bfloat162(lo, hi);
    return *reinterpret_cast<uint32_t*>(&p);
}

// Split W[K x 256] into packed bf16 hi/lo with k-pairs in one uint32.
__global__ void split_w_k(const float* __restrict__ W, int k2n) {
    int idx = blockIdx.x * blockDim.x + threadIdx.x;
    if (idx < k2n) {
        int k2 = idx >> 8, n = idx & 255;
        float w0 = W[(2 * k2) * 256 + n];
        float w1 = W[(2 * k2 + 1) * 256 + n];
        __nv_bfloat16 h0, l0, h1, l1;
        bf16_split(w0, h0, l0);
        bf16_split(w1, h1, l1);
        g_Wph[idx] = pack_bf16(h0, h1);
        g_Wpl[idx] = pack_bf16(l0, l1);
    }
}

// ---------------------------------------------------------------------------
// bf16 3-term tensor-core GEMM + fused attention coefficients.
// feat[64 x 256] = A[64 x K] @ W[K x 256],  A=Ah+Al, W=Wh+Wl (bf16 splits),
// D = Ah*Wh + Ah*Wl + Al*Wh  (Al*Wl ~ 4e-6, dropped).
// Block: 256 thr = 8 warps, 2(M) x 4(N); warp tile m32 x n64 (1 head/warp).
// feat stored fp16 (gather BW), el/er fp32.
// ---------------------------------------------------------------------------
__device__ __forceinline__ void mma_bf16(float* c, const uint32_t* a,
                                         uint32_t b0, uint32_t b1)
{
    asm volatile(
        "mma.sync.aligned.m16n8k16.row.col.f32.bf16.bf16.f32 "
        "{%0,%1,%2,%3}, {%4,%5,%6,%7}, {%8,%9}, {%0,%1,%2,%3};"
        : "+f"(c[0]), "+f"(c[1]), "+f"(c[2]), "+f"(c[3])
        : "r"(a[0]), "r"(a[1]), "r"(a[2]), "r"(a[3]), "r"(b0), "r"(b1));
}

template <int K>
__global__ void __launch_bounds__(256) gemm_mma_k(
    const float* __restrict__ hin,
    const float* __restrict__ al, const float* __restrict__ ar)
{
    constexpr int K2  = K / 2;
    constexpr int ASp = K2 + 4;   // ≡ 4 (mod 32): A frag loads conflict-free
    constexpr int WSp = 264;      // ≡ 8 (mod 32): B frag loads conflict-free
    extern __shared__ uint32_t smu[];
    uint32_t* sAh = smu;                         // 64*ASp
    uint32_t* sAl = sAh + 64 * ASp;              // 64*ASp
    uint32_t* sWh = sAl + 64 * ASp;              // K2*WSp
    uint32_t* sWl = sWh + K2 * WSp;              // K2*WSp

    int t = threadIdx.x, lane = t & 31, wid = t >> 5;
    int wm = wid >> 2, wn = wid & 3;     // warp M-row, warp N-col (= head)
    int g = lane >> 2, q = lane & 3;     // groupID (row), quad lane
    int n0 = blockIdx.x * 64;

    // Stage A as packed bf16 hi/lo k-pairs; zero-fill rows >= NN
    for (int idx = t; idx < 64 * K2; idx += 256) {
        int r = idx / K2, k2 = idx % K2;
        float v0 = 0.f, v1 = 0.f;
        if (n0 + r < NN) {
            float2 vv = *(const float2*)&hin[(size_t)(n0 + r) * K + 2 * k2];
            v0 = vv.x; v1 = vv.y;
        }
        __nv_bfloat16 h0, l0, h1, l1;
        bf16_split(v0, h0, l0);
        bf16_split(v1, h1, l1);
        sAh[r * ASp + k2] = pack_bf16(h0, h1);
        sAl[r * ASp + k2] = pack_bf16(l0, l1);
    }
    // Stage full W (hi/lo)
    for (int idx = t; idx < K2 * 256; idx += 256) {
        int k2 = idx >> 8, n = idx & 255;
        sWh[k2 * WSp + n] = g_Wph[idx];
        sWl[k2 * WSp + n] = g_Wpl[idx];
    }
    __syncthreads();

    float c_[2][8][4];
    #pragma unroll
    for (int i = 0; i < 2; i++)
        #pragma unroll
        for (int j = 0; j < 8; j++)
            #pragma unroll
            for (int r = 0; r < 4; r++) c_[i][j][r] = 0.f;

    for (int ks = 0; ks < K / 16; ks++) {
        int k2b = ks * 8;
        uint32_t ah[2][4], alr[2][4];
        #pragma unroll
        for (int i = 0; i < 2; i++) {
            int r = wm * 32 + i * 16 + g;
            ah[i][0]  = sAh[r * ASp + k2b + q];
            ah[i][1]  = sAh[(r + 8) * ASp + k2b + q];
            ah[i][2]  = sAh[r * ASp + k2b + 4 + q];
            ah[i][3]  = sAh[(r + 8) * ASp + k2b + 4 + q];
            alr[i][0] = sAl[r * ASp + k2b + q];
            alr[i][1] = sAl[(r + 8) * ASp + k2b + q];
            alr[i][2] = sAl[r * ASp + k2b + 4 + q];
            alr[i][3] = sAl[(r + 8) * ASp + k2b + 4 + q];
        }
        #pragma unroll
        for (int j = 0; j < 8; j++) {
            int ncol = wn * 64 + j * 8 + g;
            uint32_t bh0 = sWh[(k2b + q) * WSp + ncol];
            uint32_t bh1 = sWh[(k2b + 4 + q) * WSp + ncol];
            uint32_t bl0 = sWl[(k2b + q) * WSp + ncol];
            uint32_t bl1 = sWl[(k2b + 4 + q) * WSp + ncol];
            #pragma unroll
            for (int i = 0; i < 2; i++) {
                mma_bf16(c_[i][j], ah[i], bh0, bh1);
                mma_bf16(c_[i][j], ah[i], bl0, bl1);
                mma_bf16(c_[i][j], alr[i], bh0, bh1);
            }
        }
    }

    // Epilogue: store feat (fp16), fused el/er (this warp's head = wn, fp32)
    float alv[8][2], arv[8][2];
    #pragma unroll
    for (int j = 0; j < 8; j++) {
        int col = wn * 64 + j * 8 + 2 * q;
        alv[j][0] = al[col]; alv[j][1] = al[col + 1];
        arv[j][0] = ar[col]; arv[j][1] = ar[col + 1];
    }
    #pragma unroll
    for (int i = 0; i < 2; i++) {
        int rtop = n0 + wm * 32 + i * 16 + g;
        int rbot = rtop + 8;
        float plt = 0.f, prt = 0.f, plb = 0.f, prb = 0.f;
        #pragma unroll
        for (int j = 0; j < 8; j++) {
            int cb = wn * 64 + j * 8 + 2 * q;
            if (rtop < NN)
                *(__half2*)&g_feat_h[(size_t)rtop * HD + cb] =
                    __floats2half2_rn(c_[i][j][0], c_[i][j][1]);
            if (rbot < NN)
                *(__half2*)&g_feat_h[(size_t)rbot * HD + cb] =
                    __floats2half2_rn(c_[i][j][2], c_[i][j][3]);
            plt += c_[i][j][0] * alv[j][0] + c_[i][j][1] * alv[j][1];
            prt += c_[i][j][0] * arv[j][0] + c_[i][j][1] * arv[j][1];
            plb += c_[i][j][2] * alv[j][0] + c_[i][j][3] * alv[j][1];
            prb += c_[i][j][2] * arv[j][0] + c_[i][j][3] * arv[j][1];
        }
        #pragma unroll
        for (int o = 1; o <= 2; o <<= 1) {
            plt += __shfl_xor_sync(0xffffffffu, plt, o);
            prt += __shfl_xor_sync(0xffffffffu, prt, o);
            plb += __shfl_xor_sync(0xffffffffu, plb, o);
            prb += __shfl_xor_sync(0xffffffffu, prb, o);
        }
        if (q == 0) {
            if (rtop < NN) { g_el[rtop * HH + wn] = plt; g_er[rtop * HH + wn] = prt; }
            if (rbot < NN) { g_el[rbot * HH + wn] = plb; g_er[rbot * HH + wn] = prb; }
        }
    }
}

// ---------------------------------------------------------------------------
// Edge softmax + weighted aggregation. One block (128 thr) per dst node,
// warp h handles head h. CSR gather of fp16 feat (half2/lane = 128B/warp/edge),
// fp32 accumulate, no atomics, gather loop unrolled x4.
// ---------------------------------------------------------------------------
template <bool MEAN>
__global__ void __launch_bounds__(128) edge_agg_k(
    const float* __restrict__ b, float* __restrict__ out)
{
    constexpr int MAXDEG = 64;
    int n = blockIdx.x;
    int t = threadIdx.x, lane = t & 31, h = t >> 5;
    int rb = g_rowptr[n];
    int deg = g_rowptr[n + 1] - rb;

    __shared__ int   s_src[MAXDEG];
    __shared__ float s_w[HH][MAXDEG];
    __shared__ float s_out[HH][DD];

    float2 acc = make_float2(0.f, 0.f);
    const __half2* fb = (const __half2*)g_feat_h + (h * 32 + lane);

    if (deg > 0 && deg <= MAXDEG) {
        float4 er4 = *(const float4*)(g_er + n * HH);
        if (t < MAXDEG && t < deg) {
            int j = t;
            int sn = g_csr[rb + j];
            s_src[j] = sn;
            float4 el4 = *(const float4*)(g_el + sn * HH);
            float e0 = el4.x + er4.x; s_w[0][j] = e0 > 0.f ? e0 : NEG_SLOPE * e0;
            float e1 = el4.y + er4.y; s_w[1][j] = e1 > 0.f ? e1 : NEG_SLOPE * e1;
            float e2 = el4.z + er4.z; s_w[2][j] = e2 > 0.f ? e2 : NEG_SLOPE * e2;
            float e3 = el4.w + er4.w; s_w[3][j] = e3 > 0.f ? e3 : NEG_SLOPE * e3;
        }
        __syncthreads();

        float m = -1e30f;
        for (int j = lane; j < deg; j += 32) m = fmaxf(m, s_w[h][j]);
        #pragma unroll
        for (int o = 16; o; o >>= 1) m = fmaxf(m, __shfl_xor_sync(0xffffffffu, m, o));
        float s = 0.f;
        for (int j = lane; j < deg; j += 32) {
            float w = __expf(s_w[h][j] - m);
            s_w[h][j] = w;
            s += w;
        }
        #pragma unroll
        for (int o = 16; o; o >>= 1) s += __shfl_xor_sync(0xffffffffu, s, o);
        float inv = 1.0f / s;
        __syncwarp();

        int j = 0;
        for (; j + 4 <= deg; j += 4) {
            int   s0 = s_src[j],     s1 = s_src[j + 1];
            int   s2 = s_src[j + 2], s3 = s_src[j + 3];
            float w0 = s_w[h][j],     w1 = s_w[h][j + 1];
            float w2 = s_w[h][j + 2], w3 = s_w[h][j + 3];
            float2 f0 = __half22float2(fb[(size_t)s0 * 128]);
            float2 f1 = __half22float2(fb[(size_t)s1 * 128]);
            float2 f2 = __half22float2(fb[(size_t)s2 * 128]);
            float2 f3 = __half22float2(fb[(size_t)s3 * 128]);
            acc.x += w0 * f0.x; acc.y += w0 * f0.y;
            acc.x += w1 * f1.x; acc.y += w1 * f1.y;
            acc.x += w2 * f2.x; acc.y += w2 * f2.y;
            acc.x += w3 * f3.x; acc.y += w3 * f3.y;
        }
        for (; j < deg; j++) {
            float w = s_w[h][j];
            float2 f = __half22float2(fb[(size_t)s_src[j] * 128]);
            acc.x += w * f.x; acc.y += w * f.y;
        }
        acc.x *= inv; acc.y *= inv;
    } else if (deg > MAXDEG) {
        float er_h = g_er[n * HH + h];
        float m = -1e30f;
        for (int j = lane; j < deg; j += 32) {
            int sn = g_csr[rb + j];
            float e = g_el[sn * HH + h] + er_h;
            e = e > 0.f ? e : NEG_SLOPE * e;
            m = fmaxf(m, e);
        }
        #pragma unroll
        for (int o = 16; o; o >>= 1) m = fmaxf(m, __shfl_xor_sync(0xffffffffu, m, o));
        float s = 0.f;
        for (int j = lane; j < deg; j += 32) {
            int sn = g_csr[rb + j];
            float e = g_el[sn * HH + h] + er_h;
            e = e > 0.f ? e : NEG_SLOPE * e;
            s += __expf(e - m);
        }
        #pragma unroll
        for (int o = 16; o; o >>= 1) s += __shfl_xor_sync(0xffffffffu, s, o);
        float inv = 1.0f / s;
        for (int j = 0; j < deg; j++) {
            int sn = g_csr[rb + j];
            float e = g_el[sn * HH + h] + er_h;
            e = e > 0.f ? e : NEG_SLOPE * e;
            float w = __expf(e - m);
            float2 f = __half22float2(fb[(size_t)sn * 128]);
            acc.x += w * f.x; acc.y += w * f.y;
        }
        acc.x *= inv; acc.y *= inv;
    }

    if (MEAN) {
        s_out[h][2 * lane]     = acc.x;
        s_out[h][2 * lane + 1] = acc.y;
        __syncthreads();
        if (t < DD) {
            float v = 0.25f * (s_out[0][t] + s_out[1][t] + s_out[2][t] + s_out[3][t])
                    + 0.25f * (b[t] + b[DD + t] + b[2 * DD + t] + b[3 * DD + t]);
            out[(size_t)n * DD + t] = v;
        }
    } else {
        int o = h * DD + 2 * lane;
        float2 bb = *(const float2*)(b + o);
        float2 r;
        r.x = acc.x + bb.x;
        r.y = acc.y + bb.y;
        *(float2*)(out + (size_t)n * HD + o) = r;
    }
}

// ---------------------------------------------------------------------------
// Final Linear(256->64) + LayerNorm (no affine). 16 nodes/block, 64 threads.
// ---------------------------------------------------------------------------
__global__ void __launch_bounds__(64) final_ln_k(
    const float* __restrict__ hin, const float* __restrict__ Wo,
    const float* __restrict__ bo, float* __restrict__ out)
{
    constexpr int NB = 16;
    constexpr int K4 = HD / 4;               // 64
    __shared__ float4 sh4[NB * K4];          // 16 KB
    __shared__ float so[NB * DD];            // 4 KB
    __shared__ float mu_s[NB], rs_s[NB];
    int t = threadIdx.x;
    int n0 = blockIdx.x * NB;

    const float4* hin4 = (const float4*)(hin + (size_t)n0 * HD);
    for (int idx = t; idx < NB * K4; idx += 64)
        sh4[idx] = hin4[idx];
    __syncthreads();

    float acc[NB];
    #pragma unroll
    for (int i = 0; i < NB; i++) acc[i] = 0.f;
    float bv = bo[t];

    for (int k4 = 0; k4 < K4; k4++) {
        int k = k4 * 4;
        float w0 = __ldg(&Wo[(k + 0) * DD + t]);
        float w1 = __ldg(&Wo[(k + 1) * DD + t]);
        float w2 = __ldg(&Wo[(k + 2) * DD + t]);
        float w3 = __ldg(&Wo[(k + 3) * DD + t]);
        #pragma unroll
        for (int i = 0; i < NB; i++) {
            float4 s = sh4[i * K4 + k4];
            acc[i] += s.x * w0;
            acc[i] += s.y * w1;
            acc[i] += s.z * w2;
            acc[i] += s.w * w3;
        }
    }

    #pragma unroll
    for (int i = 0; i < NB; i++) so[i * DD + t] = acc[i] + bv;
    __syncthreads();

    if (t < NB) {
        float s = 0.f;
        for (int j = 0; j < DD; j++) s += so[t * DD + j];
        float mu = s * (1.0f / DD);
        float s2 = 0.f;
        for (int j = 0; j < DD; j++) {
            float d = so[t * DD + j] - mu;
            s2 += d * d;
        }
        mu_s[t] = mu;
        rs_s[t] = rsqrtf(s2 * (1.0f / DD) + 1e-5f);
    }
    __syncthreads();

    #pragma unroll
    for (int i = 0; i < NB; i++)
        out[(size_t)(n0 + i) * DD + t] = (so[i * DD + t] - mu_s[i]) * rs_s[i];
}

// ---------------------------------------------------------------------------
// Launch: inputs (metadata order):
// 0 in_feat[N,128] 1 src[E] 2 dst[E] 3 W1[128,256] 4 al1[4,64] 5 ar1[4,64]
// 6 b1[256] 7 Wh[3,64,256] 8 alh[3,4,64] 9 arh[3,4,64] 10 bh[3,256]
// 11 Wo[256,64] 12 bo[64]  -> out float32 [N,64]
// ---------------------------------------------------------------------------
extern "C" void kernel_launch(void* const* d_in, const int* in_sizes, int n_in,
                              void* d_out, int out_size)
{
    const float* in_feat = (const float*)d_in[0];
    const int*   src     = (const int*)d_in[1];
    const int*   dst     = (const int*)d_in[2];
    const float* W1      = (const float*)d_in[3];
    const float* al1     = (const float*)d_in[4];
    const float* ar1     = (const float*)d_in[5];
    const float* b1      = (const float*)d_in[6];
    const float* Whp     = (const float*)d_in[7];
    const float* alh     = (const float*)d_in[8];
    const float* arh     = (const float*)d_in[9];
    const float* bh      = (const float*)d_in[10];
    const float* Wo      = (const float*)d_in[11];
    const float* bo      = (const float*)d_in[12];
    float* out = (float*)d_out;

    float* g_h_ptr;
    cudaGetSymbolAddress((void**)&g_h_ptr, g_h);

    // smem: 2*64*ASp + 2*K2*WSp uint32
    const int SMEM1 = (2 * 64 * (IN_F / 2 + 4) + 2 * (IN_F / 2) * 264) * 4; // 169984
    const int SMEMH = (2 * 64 * (DD / 2 + 4) + 2 * (DD / 2) * 264) * 4;     //  86016
    cudaFuncSetAttribute(gemm_mma_k<IN_F>,
                         cudaFuncAttributeMaxDynamicSharedMemorySize, SMEM1);
    cudaFuncSetAttribute(gemm_mma_k<DD>,
                         cudaFuncAttributeMaxDynamicSharedMemorySize, SMEMH);

    // CSR build
    zero_cur_k<<<(NN + 255) / 256, 256>>>();
    hist_k<<<(EE + 255) / 256, 256>>>(dst);
    scan_k<<<1, 1024>>>();
    scatter_k<<<(EE + 255) / 256, 256>>>(src, dst);

    const int GMMA = (NN + 63) / 64;   // 782 blocks

    // Layer 1: conv1 (K=128), mean over heads -> g_h[N,64]
    split_w_k<<<((IN_F / 2) * HD + 255) / 256, 256>>>(W1, (IN_F / 2) * HD);
    gemm_mma_k<IN_F><<<GMMA, 256, SMEM1>>>(in_feat, al1, ar1);
    edge_agg_k<true><<<NN, 128>>>(b1, g_h_ptr);

    // Hidden layers 0,1 (mean)
    for (int l = 0; l < 2; l++) {
        split_w_k<<<((DD / 2) * HD + 255) / 256, 256>>>(Whp + (size_t)l * DD * HD,
                                                        (DD / 2) * HD);
        gemm_mma_k<DD><<<GMMA, 256, SMEMH>>>(g_h_ptr, alh + l * HD, arh + l * HD);
        edge_agg_k<true><<<NN, 128>>>(bh + l * HD, g_h_ptr);
    }

    // Hidden layer 2 (full [N,H,D] output)
    split_w_k<<<((DD / 2) * HD + 255) / 256, 256>>>(Whp + (size_t)2 * DD * HD,
                                                    (DD / 2) * HD);
    gemm_mma_k<DD><<<GMMA, 256, SMEMH>>>(g_h_ptr, alh + 2 * HD, arh + 2 * HD);
    edge_agg_k<false><<<NN, 128>>>(bh + 2 * HD, g_h_ptr);

    // Final linear + LayerNorm -> d_out
    final_ln_k<<<NN / 16, 64>>>(g_h_ptr, Wo, bo, out);
}

// round 8
// speedup vs baseline: 1.4094x; 1.1808x over previous
#include <cuda_runtime.h>
#include <cuda_bf16.h>
#include <cuda_fp16.h>
#include <cstdint>

// Problem constants (match reference_code)
#define NN 50000      // nodes
#define EE 800000     // edges
#define IN_F 128
#define DD 64
#define HH 4
#define HD 256        // H*D
#define NEG_SLOPE 0.2f

// ---------------------------------------------------------------------------
// Scratch (static __device__ arrays — no allocation allowed)
// ---------------------------------------------------------------------------
__device__ __half   g_feat_h[(size_t)NN * HD]; // projected features [N,256] fp16
__device__ float    g_h[(size_t)NN * HD];      // layer io buffer (fp32)
__device__ float    g_el[(size_t)NN * HH];
__device__ float    g_er[(size_t)NN * HH];
__device__ int      g_rowptr[NN + 1];
__device__ int      g_cur[NN];
__device__ int      g_csr[EE];                 // src per CSR slot (sorted by dst)
__device__ uint32_t g_Wph[(IN_F / 2) * HD];    // W bf16-high, k-pairs packed
__device__ uint32_t g_Wpl[(IN_F / 2) * HD];    // W bf16-low,  k-pairs packed

// ---------------------------------------------------------------------------
// CSR build: zero -> histogram(dst) -> scan -> scatter
// ---------------------------------------------------------------------------
__global__ void zero_cur_k() {
    int i = blockIdx.x * blockDim.x + threadIdx.x;
    if (i < NN) g_cur[i] = 0;
}

__global__ void hist_k(const int* __restrict__ dst) {
    int e = blockIdx.x * blockDim.x + threadIdx.x;
    if (e < EE) atomicAdd(&g_cur[dst[e]], 1);
}

// single-block exclusive scan over g_cur -> g_rowptr; 4 elems/thread/iter.
// Also re-zeros g_cur. NN % 4 == 0.
__global__ void scan_k() {
    __shared__ int ws[32];
    __shared__ int s_carry;
    int t = threadIdx.x, lane = t & 31, wid = t >> 5;
    if (t == 0) s_carry = 0;
    __syncthreads();
    for (int base = 0; base < NN; base += 4096) {
        int i0 = base + t * 4;
        int4 v = make_int4(0, 0, 0, 0);
        if (i0 < NN) {
            v = *(const int4*)&g_cur[i0];
            *(int4*)&g_cur[i0] = make_int4(0, 0, 0, 0);
        }
        int tsum = v.x + v.y + v.z + v.w;
        int x = tsum;
        #pragma unroll
        for (int o = 1; o < 32; o <<= 1) {
            int y = __shfl_up_sync(0xffffffffu, x, o);
            if (lane >= o) x += y;
        }
        if (lane == 31) ws[wid] = x;
        __syncthreads();
        if (wid == 0) {
            int y = ws[lane];
            #pragma unroll
            for (int o = 1; o < 32; o <<= 1) {
                int z = __shfl_up_sync(0xffffffffu, y, o);
                if (lane >= o) y += z;
            }
            ws[lane] = y;
        }
        __syncthreads();
        int excl = x - tsum + (wid ? ws[wid - 1] : 0) + s_carry;
        if (i0 < NN) {
            g_rowptr[i0]     = excl;
            g_rowptr[i0 + 1] = excl + v.x;
            g_rowptr[i0 + 2] = excl + v.x + v.y;
            g_rowptr[i0 + 3] = excl + v.x + v.y + v.z;
        }
        int total = ws[31];
        __syncthreads();
        if (t == 0) s_carry += total;
        __syncthreads();
    }
    if (t == 0) g_rowptr[NN] = s_carry;
}

__global__ void scatter_k(const int* __restrict__ src, const int* __restrict__ dst) {
    int e = blockIdx.x * blockDim.x + threadIdx.x;
    if (e < EE) {
        int d = dst[e];
        int pos = g_rowptr[d] + atomicAdd(&g_cur[d], 1);
        g_csr[pos] = src[e];
    }
}

// ---------------------------------------------------------------------------
// bf16 split helpers
// ---------------------------------------------------------------------------
__device__ __forceinline__ void bf16_split(float v, __nv_bfloat16& h, __nv_bfloat16& l) {
    h = __float2bfloat16_rn(v);
    l = __float2bfloat16_rn(v - __bfloat162float(h));
}
__device__ __forceinline__ uint32_t pack_bf16(__nv_bfloat16 lo, __nv_bfloat16 hi) {
    __nv_bfloat162 p = __halves2bfloat162(lo, hi);
    return *reinterpret_cast<uint32_t*>(&p);
}

// Split W[K x 256] into packed bf16 hi/lo with k-pairs in one uint32.
__global__ void split_w_k(const float* __restrict__ W, int k2n) {
    int idx = blockIdx.x * blockDim.x + threadIdx.x;
    if (idx < k2n) {
        int k2 = idx >> 8, n = idx & 255;
        float w0 = W[(2 * k2) * 256 + n];
        float w1 = W[(2 * k2 + 1) * 256 + n];
        __nv_bfloat16 h0, l0, h1, l1;
        bf16_split(w0, h0, l0);
        bf16_split(w1, h1, l1);
        g_Wph[idx] = pack_bf16(h0, h1);
        g_Wpl[idx] = pack_bf16(l0, l1);
    }
}

// ---------------------------------------------------------------------------
// bf16 3-term tensor-core GEMM + fused attention coefficients.
// ---------------------------------------------------------------------------
__device__ __forceinline__ void mma_bf16(float* c, const uint32_t* a,
                                         uint32_t b0, uint32_t b1)
{
    asm volatile(
        "mma.sync.aligned.m16n8k16.row.col.f32.bf16.bf16.f32 "
        "{%0,%1,%2,%3}, {%4,%5,%6,%7}, {%8,%9}, {%0,%1,%2,%3};"
        : "+f"(c[0]), "+f"(c[1]), "+f"(c[2]), "+f"(c[3])
        : "r"(a[0]), "r"(a[1]), "r"(a[2]), "r"(a[3]), "r"(b0), "r"(b1));
}

template <int K>
__global__ void __launch_bounds__(256) gemm_mma_k(
    const float* __restrict__ hin,
    const float* __restrict__ al, const float* __restrict__ ar)
{
    constexpr int K2  = K / 2;
    constexpr int ASp = K2 + 4;   // ≡ 4 (mod 32): A frag loads conflict-free
    constexpr int WSp = 264;      // ≡ 8 (mod 32): B frag loads conflict-free
    extern __shared__ uint32_t smu[];
    uint32_t* sAh = smu;                         // 64*ASp
    uint32_t* sAl = sAh + 64 * ASp;              // 64*ASp
    uint32_t* sWh = sAl + 64 * ASp;              // K2*WSp
    uint32_t* sWl = sWh + K2 * WSp;              // K2*WSp

    int t = threadIdx.x, lane = t & 31, wid = t >> 5;
    int wm = wid >> 2, wn = wid & 3;     // warp M-row, warp N-col (= head)
    int g = lane >> 2, q = lane & 3;     // groupID (row), quad lane
    int n0 = blockIdx.x * 64;

    // Stage A as packed bf16 hi/lo k-pairs; zero-fill rows >= NN
    for (int idx = t; idx < 64 * K2; idx += 256) {
        int r = idx / K2, k2 = idx % K2;
        float v0 = 0.f, v1 = 0.f;
        if (n0 + r < NN) {
            float2 vv = *(const float2*)&hin[(size_t)(n0 + r) * K + 2 * k2];
            v0 = vv.x; v1 = vv.y;
        }
        __nv_bfloat16 h0, l0, h1, l1;
        bf16_split(v0, h0, l0);
        bf16_split(v1, h1, l1);
        sAh[r * ASp + k2] = pack_bf16(h0, h1);
        sAl[r * ASp + k2] = pack_bf16(l0, l1);
    }
    // Stage full W (hi/lo)
    for (int idx = t; idx < K2 * 256; idx += 256) {
        int k2 = idx >> 8, n = idx & 255;
        sWh[k2 * WSp + n] = g_Wph[idx];
        sWl[k2 * WSp + n] = g_Wpl[idx];
    }
    __syncthreads();

    float c_[2][8][4];
    #pragma unroll
    for (int i = 0; i < 2; i++)
        #pragma unroll
        for (int j = 0; j < 8; j++)
            #pragma unroll
            for (int r = 0; r < 4; r++) c_[i][j][r] = 0.f;

    for (int ks = 0; ks < K / 16; ks++) {
        int k2b = ks * 8;
        uint32_t ah[2][4], alr[2][4];
        #pragma unroll
        for (int i = 0; i < 2; i++) {
            int r = wm * 32 + i * 16 + g;
            ah[i][0]  = sAh[r * ASp + k2b + q];
            ah[i][1]  = sAh[(r + 8) * ASp + k2b + q];
            ah[i][2]  = sAh[r * ASp + k2b + 4 + q];
            ah[i][3]  = sAh[(r + 8) * ASp + k2b + 4 + q];
            alr[i][0] = sAl[r * ASp + k2b + q];
            alr[i][1] = sAl[(r + 8) * ASp + k2b + q];
            alr[i][2] = sAl[r * ASp + k2b + 4 + q];
            alr[i][3] = sAl[(r + 8) * ASp + k2b + 4 + q];
        }
        #pragma unroll
        for (int j = 0; j < 8; j++) {
            int ncol = wn * 64 + j * 8 + g;
            uint32_t bh0 = sWh[(k2b + q) * WSp + ncol];
            uint32_t bh1 = sWh[(k2b + 4 + q) * WSp + ncol];
            uint32_t bl0 = sWl[(k2b + q) * WSp + ncol];
            uint32_t bl1 = sWl[(k2b + 4 + q) * WSp + ncol];
            #pragma unroll
            for (int i = 0; i < 2; i++) {
                mma_bf16(c_[i][j], ah[i], bh0, bh1);
                mma_bf16(c_[i][j], ah[i], bl0, bl1);
                mma_bf16(c_[i][j], alr[i], bh0, bh1);
            }
        }
    }

    // Epilogue: store feat (fp16), fused el/er (this warp's head = wn, fp32)
    float alv[8][2], arv[8][2];
    #pragma unroll
    for (int j = 0; j < 8; j++) {
        int col = wn * 64 + j * 8 + 2 * q;
        alv[j][0] = al[col]; alv[j][1] = al[col + 1];
        arv[j][0] = ar[col]; arv[j][1] = ar[col + 1];
    }
    #pragma unroll
    for (int i = 0; i < 2; i++) {
        int rtop = n0 + wm * 32 + i * 16 + g;
        int rbot = rtop + 8;
        float plt = 0.f, prt = 0.f, plb = 0.f, prb = 0.f;
        #pragma unroll
        for (int j = 0; j < 8; j++) {
            int cb = wn * 64 + j * 8 + 2 * q;
            if (rtop < NN)
                *(__half2*)&g_feat_h[(size_t)rtop * HD + cb] =
                    __floats2half2_rn(c_[i][j][0], c_[i][j][1]);
            if (rbot < NN)
                *(__half2*)&g_feat_h[(size_t)rbot * HD + cb] =
                    __floats2half2_rn(c_[i][j][2], c_[i][j][3]);
            plt += c_[i][j][0] * alv[j][0] + c_[i][j][1] * alv[j][1];
            prt += c_[i][j][0] * arv[j][0] + c_[i][j][1] * arv[j][1];
            plb += c_[i][j][2] * alv[j][0] + c_[i][j][3] * alv[j][1];
            prb += c_[i][j][2] * arv[j][0] + c_[i][j][3] * arv[j][1];
        }
        #pragma unroll
        for (int o = 1; o <= 2; o <<= 1) {
            plt += __shfl_xor_sync(0xffffffffu, plt, o);
            prt += __shfl_xor_sync(0xffffffffu, prt, o);
            plb += __shfl_xor_sync(0xffffffffu, plb, o);
            prb += __shfl_xor_sync(0xffffffffu, prb, o);
        }
        if (q == 0) {
            if (rtop < NN) { g_el[rtop * HH + wn] = plt; g_er[rtop * HH + wn] = prt; }
            if (rbot < NN) { g_el[rbot * HH + wn] = plb; g_er[rbot * HH + wn] = prb; }
        }
    }
}

// ---------------------------------------------------------------------------
// Warp-per-node edge softmax + aggregation. 256 thr = 8 warps = 8 nodes/block.
// Lane c owns 16B (8 halves) of the 512B fp16 feature row -> gather is one
// LDG.128/lane/edge. All 4 heads inside the warp; no block barriers.
// Fast path deg<=32 (lane j owns edge j); serial fallback for larger.
// ---------------------------------------------------------------------------
__device__ __forceinline__ float lrelu(float e) {
    return e > 0.f ? e : NEG_SLOPE * e;
}

template <bool MEAN>
__global__ void __launch_bounds__(256) edge_agg_w(
    const float* __restrict__ b, float* __restrict__ out)
{
    __shared__ float s_w_all[8][HH][33];
    __shared__ int   s_src_all[8][32];

    int t = threadIdx.x, lane = t & 31, wid = t >> 5;
    int n = blockIdx.x * 8 + wid;
    if (n >= NN) return;

    float (*s_w)[33] = s_w_all[wid];
    int* s_src = s_src_all[wid];

    int rb  = g_rowptr[n];
    int deg = g_rowptr[n + 1] - rb;

    int h = lane >> 3;           // head owning this lane's 8 features
    float acc[8];
    #pragma unroll
    for (int i = 0; i < 8; i++) acc[i] = 0.f;

    const uint4* fb = (const uint4*)g_feat_h;   // 32 uint4 per node row

    if (deg > 0 && deg <= 32) {
        float4 er4 = *(const float4*)(g_er + n * HH);
        float e0 = -1e30f, e1 = -1e30f, e2 = -1e30f, e3 = -1e30f;
        if (lane < deg) {
            int sn = g_csr[rb + lane];
            s_src[lane] = sn;
            float4 el4 = *(const float4*)(g_el + sn * HH);
            e0 = lrelu(el4.x + er4.x);
            e1 = lrelu(el4.y + er4.y);
            e2 = lrelu(el4.z + er4.z);
            e3 = lrelu(el4.w + er4.w);
        }
        // per-head max
        float m0 = e0, m1 = e1, m2 = e2, m3 = e3;
        #pragma unroll
        for (int o = 16; o; o >>= 1) {
            m0 = fmaxf(m0, __shfl_xor_sync(0xffffffffu, m0, o));
            m1 = fmaxf(m1, __shfl_xor_sync(0xffffffffu, m1, o));
            m2 = fmaxf(m2, __shfl_xor_sync(0xffffffffu, m2, o));
            m3 = fmaxf(m3, __shfl_xor_sync(0xffffffffu, m3, o));
        }
        float w0 = 0.f, w1 = 0.f, w2 = 0.f, w3 = 0.f;
        if (lane < deg) {
            w0 = __expf(e0 - m0);
            w1 = __expf(e1 - m1);
            w2 = __expf(e2 - m2);
            w3 = __expf(e3 - m3);
        }
        float s0 = w0, s1 = w1, s2 = w2, s3 = w3;
        #pragma unroll
        for (int o = 16; o; o >>= 1) {
            s0 += __shfl_xor_sync(0xffffffffu, s0, o);
            s1 += __shfl_xor_sync(0xffffffffu, s1, o);
            s2 += __shfl_xor_sync(0xffffffffu, s2, o);
            s3 += __shfl_xor_sync(0xffffffffu, s3, o);
        }
        if (lane < deg) {
            s_w[0][lane] = w0 / s0;
            s_w[1][lane] = w1 / s1;
            s_w[2][lane] = w2 / s2;
            s_w[3][lane] = w3 / s3;
        }
        __syncwarp();

        for (int j = 0; j < deg; j++) {
            int   sn = s_src[j];
            float w  = s_w[h][j];
            uint4 f  = fb[(size_t)sn * 32 + lane];
            float2 p0 = __half22float2(*(const __half2*)&f.x);
            float2 p1 = __half22float2(*(const __half2*)&f.y);
            float2 p2 = __half22float2(*(const __half2*)&f.z);
            float2 p3 = __half22float2(*(const __half2*)&f.w);
            acc[0] += w * p0.x; acc[1] += w * p0.y;
            acc[2] += w * p1.x; acc[3] += w * p1.y;
            acc[4] += w * p2.x; acc[5] += w * p2.y;
            acc[6] += w * p3.x; acc[7] += w * p3.y;
        }
    } else if (deg > 32) {
        // rare fallback (~1e-4 of nodes): serial per-lane softmax on own head
        float er_h = g_er[n * HH + h];
        float m = -1e30f;
        for (int j = 0; j < deg; j++) {
            int sn = g_csr[rb + j];
            m = fmaxf(m, lrelu(g_el[sn * HH + h] + er_h));
        }
        float s = 0.f;
        for (int j = 0; j < deg; j++) {
            int sn = g_csr[rb + j];
            s += __expf(lrelu(g_el[sn * HH + h] + er_h) - m);
        }
        float inv = 1.0f / s;
        for (int j = 0; j < deg; j++) {
            int sn = g_csr[rb + j];
            float w = __expf(lrelu(g_el[sn * HH + h] + er_h) - m) * inv;
            uint4 f = fb[(size_t)sn * 32 + lane];
            float2 p0 = __half22float2(*(const __half2*)&f.x);
            float2 p1 = __half22float2(*(const __half2*)&f.y);
            float2 p2 = __half22float2(*(const __half2*)&f.z);
            float2 p3 = __half22float2(*(const __half2*)&f.w);
            acc[0] += w * p0.x; acc[1] += w * p0.y;
            acc[2] += w * p1.x; acc[3] += w * p1.y;
            acc[4] += w * p2.x; acc[5] += w * p2.y;
            acc[6] += w * p3.x; acc[7] += w * p3.y;
        }
    }

    if (MEAN) {
        // lanes c, c+8, c+16, c+24 hold heads 0..3 at same feature offsets
        #pragma unroll
        for (int o = 8; o <= 16; o <<= 1)
            #pragma unroll
            for (int i = 0; i < 8; i++)
                acc[i] += __shfl_down_sync(0xffffffffu, acc[i], o);
        if (lane < 8) {
            int d0 = lane * 8;
            float r[8];
            #pragma unroll
            for (int i = 0; i < 8; i++) {
                int d = d0 + i;
                r[i] = 0.25f * (acc[i] + b[d] + b[DD + d] + b[2 * DD + d] + b[3 * DD + d]);
            }
            float4* o4 = (float4*)(out + (size_t)n * DD + d0);
            o4[0] = make_float4(r[0], r[1], r[2], r[3]);
            o4[1] = make_float4(r[4], r[5], r[6], r[7]);
        }
    } else {
        int d0 = lane * 8;
        float r[8];
        #pragma unroll
        for (int i = 0; i < 8; i++) r[i] = acc[i] + b[d0 + i];
        float4* o4 = (float4*)(out + (size_t)n * HD + d0);
        o4[0] = make_float4(r[0], r[1], r[2], r[3]);
        o4[1] = make_float4(r[4], r[5], r[6], r[7]);
    }
}

// ---------------------------------------------------------------------------
// Final Linear(256->64) + LayerNorm (no affine). 16 nodes/block, 64 threads.
// ---------------------------------------------------------------------------
__global__ void __launch_bounds__(64) final_ln_k(
    const float* __restrict__ hin, const float* __restrict__ Wo,
    const float* __restrict__ bo, float* __restrict__ out)
{
    constexpr int NB = 16;
    constexpr int K4 = HD / 4;               // 64
    __shared__ float4 sh4[NB * K4];          // 16 KB
    __shared__ float so[NB * DD];            // 4 KB
    __shared__ float mu_s[NB], rs_s[NB];
    int t = threadIdx.x;
    int n0 = blockIdx.x * NB;

    const float4* hin4 = (const float4*)(hin + (size_t)n0 * HD);
    for (int idx = t; idx < NB * K4; idx += 64)
        sh4[idx] = hin4[idx];
    __syncthreads();

    float acc[NB];
    #pragma unroll
    for (int i = 0; i < NB; i++) acc[i] = 0.f;
    float bv = bo[t];

    for (int k4 = 0; k4 < K4; k4++) {
        int k = k4 * 4;
        float w0 = __ldg(&Wo[(k + 0) * DD + t]);
        float w1 = __ldg(&Wo[(k + 1) * DD + t]);
        float w2 = __ldg(&Wo[(k + 2) * DD + t]);
        float w3 = __ldg(&Wo[(k + 3) * DD + t]);
        #pragma unroll
        for (int i = 0; i < NB; i++) {
            float4 s = sh4[i * K4 + k4];
            acc[i] += s.x * w0;
            acc[i] += s.y * w1;
            acc[i] += s.z * w2;
            acc[i] += s.w * w3;
        }
    }

    #pragma unroll
    for (int i = 0; i < NB; i++) so[i * DD + t] = acc[i] + bv;
    __syncthreads();

    if (t < NB) {
        float s = 0.f;
        for (int j = 0; j < DD; j++) s += so[t * DD + j];
        float mu = s * (1.0f / DD);
        float s2 = 0.f;
        for (int j = 0; j < DD; j++) {
            float d = so[t * DD + j] - mu;
            s2 += d * d;
        }
        mu_s[t] = mu;
        rs_s[t] = rsqrtf(s2 * (1.0f / DD) + 1e-5f);
    }
    __syncthreads();

    #pragma unroll
    for (int i = 0; i < NB; i++)
        out[(size_t)(n0 + i) * DD + t] = (so[i * DD + t] - mu_s[i]) * rs_s[i];
}

// ---------------------------------------------------------------------------
// Launch: inputs (metadata order):
// 0 in_feat[N,128] 1 src[E] 2 dst[E] 3 W1[128,256] 4 al1[4,64] 5 ar1[4,64]
// 6 b1[256] 7 Wh[3,64,256] 8 alh[3,4,64] 9 arh[3,4,64] 10 bh[3,256]
// 11 Wo[256,64] 12 bo[64]  -> out float32 [N,64]
// ---------------------------------------------------------------------------
extern "C" void kernel_launch(void* const* d_in, const int* in_sizes, int n_in,
                              void* d_out, int out_size)
{
    const float* in_feat = (const float*)d_in[0];
    const int*   src     = (const int*)d_in[1];
    const int*   dst     = (const int*)d_in[2];
    const float* W1      = (const float*)d_in[3];
    const float* al1     = (const float*)d_in[4];
    const float* ar1     = (const float*)d_in[5];
    const float* b1      = (const float*)d_in[6];
    const float* Whp     = (const float*)d_in[7];
    const float* alh     = (const float*)d_in[8];
    const float* arh     = (const float*)d_in[9];
    const float* bh      = (const float*)d_in[10];
    const float* Wo      = (const float*)d_in[11];
    const float* bo      = (const float*)d_in[12];
    float* out = (float*)d_out;

    float* g_h_ptr;
    cudaGetSymbolAddress((void**)&g_h_ptr, g_h);

    // smem: 2*64*ASp + 2*K2*WSp uint32
    const int SMEM1 = (2 * 64 * (IN_F / 2 + 4) + 2 * (IN_F / 2) * 264) * 4; // 169984
    const int SMEMH = (2 * 64 * (DD / 2 + 4) + 2 * (DD / 2) * 264) * 4;     //  86016
    cudaFuncSetAttribute(gemm_mma_k<IN_F>,
                         cudaFuncAttributeMaxDynamicSharedMemorySize, SMEM1);
    cudaFuncSetAttribute(gemm_mma_k<DD>,
                         cudaFuncAttributeMaxDynamicSharedMemorySize, SMEMH);

    // CSR build
    zero_cur_k<<<(NN + 255) / 256, 256>>>();
    hist_k<<<(EE + 255) / 256, 256>>>(dst);
    scan_k<<<1, 1024>>>();
    scatter_k<<<(EE + 255) / 256, 256>>>(src, dst);

    const int GMMA = (NN + 63) / 64;   // 782 blocks
    const int GAGG = (NN + 7) / 8;     // 6250 blocks (8 nodes/block)

    // Layer 1: conv1 (K=128), mean over heads -> g_h[N,64]
    split_w_k<<<((IN_F / 2) * HD + 255) / 256, 256>>>(W1, (IN_F / 2) * HD);
    gemm_mma_k<IN_F><<<GMMA, 256, SMEM1>>>(in_feat, al1, ar1);
    edge_agg_w<true><<<GAGG, 256>>>(b1, g_h_ptr);

    // Hidden layers 0,1 (mean)
    for (int l = 0; l < 2; l++) {
        split_w_k<<<((DD / 2) * HD + 255) / 256, 256>>>(Whp + (size_t)l * DD * HD,
                                                        (DD / 2) * HD);
        gemm_mma_k<DD><<<GMMA, 256, SMEMH>>>(g_h_ptr, alh + l * HD, arh + l * HD);
        edge_agg_w<true><<<GAGG, 256>>>(bh + l * HD, g_h_ptr);
    }

    // Hidden layer 2 (full [N,H,D] output)
    split_w_k<<<((DD / 2) * HD + 255) / 256, 256>>>(Whp + (size_t)2 * DD * HD,
                                                    (DD / 2) * HD);
    gemm_mma_k<DD><<<GMMA, 256, SMEMH>>>(g_h_ptr, alh + 2 * HD, arh + 2 * HD);
    edge_agg_w<false><<<GAGG, 256>>>(bh + 2 * HD, g_h_ptr);

    // Final linear + LayerNorm -> d_out
    final_ln_k<<<NN / 16, 64>>>(g_h_ptr, Wo, bo, out);
}